// round 5
// baseline (speedup 1.0000x reference)
#include <cuda_runtime.h>

// CVScaledDotProductAttention — one-pass: out = (A - mn*B)/(mx - mn)
// A = sum_k attn*v, B = sum_k (attn/|attn|)*v, mn/mx = row min/max |attn|.
// R4: 512-thread CTA (occupancy), Karatsuba complex mul (3 FMA), f32x2 packed
// over the q-pair with zero dup-movs in the phase-2 inner loop.

#define S_LEN 1024
#define NHEADS 64
#define NKT 16
#define NT 512

typedef unsigned long long u64;

__device__ __forceinline__ u64 fma2(u64 a, u64 b, u64 c) {
    u64 d; asm("fma.rn.f32x2 %0, %1, %2, %3;" : "=l"(d) : "l"(a), "l"(b), "l"(c)); return d;
}
__device__ __forceinline__ u64 mul2(u64 a, u64 b) {
    u64 d; asm("mul.rn.f32x2 %0, %1, %2;" : "=l"(d) : "l"(a), "l"(b)); return d;
}
__device__ __forceinline__ u64 add2(u64 a, u64 b) {
    u64 d; asm("add.rn.f32x2 %0, %1, %2;" : "=l"(d) : "l"(a), "l"(b)); return d;
}
__device__ __forceinline__ u64 dup2(float x) {
    u64 d; asm("mov.b64 %0, {%1, %1};" : "=l"(d) : "f"(x)); return d;
}
__device__ __forceinline__ float2 unpack2(u64 p) {
    float2 r; asm("mov.b64 {%0, %1}, %2;" : "=f"(r.x), "=f"(r.y) : "l"(p)); return r;
}

// smem layout (float offsets)
#define QR_OFF 0        // Q scalar [d][q], pre-scaled 1/8
#define QI_OFF 4096
#define QS_OFF 8192     // (qr+qi)/8
#define KR_OFF 12288    // K scalar [d][k]   (region aliased by P)
#define KI_OFF 16384
#define KS_OFF 20480    // kr+ki
#define PR_OFF 12288    // P [k][q^swz]
#define PI_OFF 16384
#define IM_OFF 20480    // 1/|p|
#define VR_OFF 24576    // V dup pairs (v,v) [k][d]: 8192 floats each
#define VI_OFF 32768
#define VS_OFF 40960    // vr+vi dup pairs
#define RMN_OFF 49152
#define RMX_OFF 49216
#define SMEM_FLOATS 49280   // 197,120 bytes

__global__ void __launch_bounds__(NT)
cvattn_kernel(const float* __restrict__ qr_g, const float* __restrict__ qi_g,
              const float* __restrict__ kr_g, const float* __restrict__ ki_g,
              const float* __restrict__ vr_g, const float* __restrict__ vi_g,
              float* __restrict__ out)
{
    extern __shared__ float sm[];
    const int tid = threadIdx.x;
    const int tx = tid & 15;           // k-group / d-group (16)
    const int ty = tid >> 4;           // q-pair index (0..31)
    const int qt = blockIdx.x;
    const int head = blockIdx.y;
    const long hb = (long)head * S_LEN * 64;

    // ---- load Q once: scalar [d][q], scaled; also qs=(qr+qi) ----
#pragma unroll
    for (int it = 0; it < 2; ++it) {
        int n = tid + it * NT;               // 0..1023
        int q = n & 63, d4 = (n >> 6) << 2;  // conflict-free transposed stores
        long g = hb + (long)(qt * 64 + q) * 64 + d4;
        float4 r4 = *(const float4*)(qr_g + g);
        float4 i4 = *(const float4*)(qi_g + g);
        float rr[4] = {r4.x, r4.y, r4.z, r4.w};
        float ii[4] = {i4.x, i4.y, i4.z, i4.w};
#pragma unroll
        for (int j = 0; j < 4; ++j) {
            float a = rr[j] * 0.125f, b = ii[j] * 0.125f;
            sm[QR_OFF + (d4 + j) * 64 + q] = a;
            sm[QI_OFF + (d4 + j) * 64 + q] = b;
            sm[QS_OFF + (d4 + j) * 64 + q] = a + b;
        }
    }
    if (tid < 64) { sm[RMN_OFF + tid] = 3.0e38f; sm[RMX_OFF + tid] = -3.0e38f; }

    // global accumulators: Karatsuba partial sums, packed over the q-pair
    u64 M1a[4], M2a[4], M3a[4], M1b[4], M2b[4], M3b[4];
#pragma unroll
    for (int l = 0; l < 4; ++l) { M1a[l]=0ull; M2a[l]=0ull; M3a[l]=0ull; M1b[l]=0ull; M2b[l]=0ull; M3b[l]=0ull; }

#pragma unroll 1
    for (int kt = 0; kt < NKT; ++kt) {
        __syncthreads();   // prev phase-2 done with P/V regions

        // ---- load K transposed scalar [d][k] (+ks), V as dup pairs [k][d] (+vs) ----
#pragma unroll
        for (int it = 0; it < 2; ++it) {
            int n = tid + it * NT;
            {   // K: (k = n&63) mapping -> conflict-free smem stores
                int k = n & 63, d4 = (n >> 6) << 2;
                long g = hb + (long)(kt * 64 + k) * 64 + d4;
                float4 r4 = *(const float4*)(kr_g + g);
                float4 i4 = *(const float4*)(ki_g + g);
                float rr[4] = {r4.x, r4.y, r4.z, r4.w};
                float ii[4] = {i4.x, i4.y, i4.z, i4.w};
#pragma unroll
                for (int j = 0; j < 4; ++j) {
                    sm[KR_OFF + (d4 + j) * 64 + k] = rr[j];
                    sm[KI_OFF + (d4 + j) * 64 + k] = ii[j];
                    sm[KS_OFF + (d4 + j) * 64 + k] = rr[j] + ii[j];
                }
            }
            {   // V: coalesced gmem mapping, dup-pair stores
                int k = n >> 4, d4 = (n & 15) << 2;
                long g = hb + (long)(kt * 64 + k) * 64 + d4;
                float4 r4 = *(const float4*)(vr_g + g);
                float4 i4 = *(const float4*)(vi_g + g);
                float rr[4] = {r4.x, r4.y, r4.z, r4.w};
                float ii[4] = {i4.x, i4.y, i4.z, i4.w};
#pragma unroll
                for (int j = 0; j < 4; ++j) {
                    int p = 2 * (k * 64 + d4 + j);
                    *(float2*)&sm[VR_OFF + p] = make_float2(rr[j], rr[j]);
                    *(float2*)&sm[VI_OFF + p] = make_float2(ii[j], ii[j]);
                    float s = rr[j] + ii[j];
                    *(float2*)&sm[VS_OFF + p] = make_float2(s, s);
                }
            }
        }
        __syncthreads();

        // ---- phase 1: Karatsuba score partials, packed over k-pairs ----
        u64 m1P[2][2], m2P[2][2], m3P[2][2];
#pragma unroll
        for (int e = 0; e < 2; ++e) { m1P[e][0]=m1P[e][1]=0ull; m2P[e][0]=m2P[e][1]=0ull; m3P[e][0]=m3P[e][1]=0ull; }

#pragma unroll 4
        for (int d = 0; d < 64; ++d) {
            float2 qrF = *(const float2*)&sm[QR_OFF + d * 64 + 2 * ty];
            float2 qiF = *(const float2*)&sm[QI_OFF + d * 64 + 2 * ty];
            float2 qsF = *(const float2*)&sm[QS_OFF + d * 64 + 2 * ty];
            u64 qrD[2] = {dup2(qrF.x), dup2(qrF.y)};
            u64 qiD[2] = {dup2(qiF.x), dup2(qiF.y)};
            u64 qsD[2] = {dup2(qsF.x), dup2(qsF.y)};
            ulonglong2 krp = *(const ulonglong2*)&sm[KR_OFF + d * 64 + 4 * tx];
            ulonglong2 kip = *(const ulonglong2*)&sm[KI_OFF + d * 64 + 4 * tx];
            ulonglong2 ksp = *(const ulonglong2*)&sm[KS_OFF + d * 64 + 4 * tx];
            u64 kr2[2] = {krp.x, krp.y};
            u64 ki2[2] = {kip.x, kip.y};
            u64 ks2[2] = {ksp.x, ksp.y};
#pragma unroll
            for (int e = 0; e < 2; ++e)
#pragma unroll
                for (int kp = 0; kp < 2; ++kp) {
                    m1P[e][kp] = fma2(qrD[e], kr2[kp], m1P[e][kp]);
                    m2P[e][kp] = fma2(qiD[e], ki2[kp], m2P[e][kp]);
                    m3P[e][kp] = fma2(qsD[e], ks2[kp], m3P[e][kp]);
                }
        }
        __syncthreads();   // K reads done; P region may be overwritten

        // ---- phase 1.5: reconstruct scores, mags, min/max, publish P ----
        float srv[2][4], siv[2][4], imv[2][4];
        float lmn[2] = {3.0e38f, 3.0e38f}, lmx[2] = {-3.0e38f, -3.0e38f};
#pragma unroll
        for (int e = 0; e < 2; ++e) {
            float m1v[4], m2v[4], m3v[4];
            { float2 t = unpack2(m1P[e][0]); m1v[0]=t.x; m1v[1]=t.y; t = unpack2(m1P[e][1]); m1v[2]=t.x; m1v[3]=t.y; }
            { float2 t = unpack2(m2P[e][0]); m2v[0]=t.x; m2v[1]=t.y; t = unpack2(m2P[e][1]); m2v[2]=t.x; m2v[3]=t.y; }
            { float2 t = unpack2(m3P[e][0]); m3v[0]=t.x; m3v[1]=t.y; t = unpack2(m3P[e][1]); m3v[2]=t.x; m3v[3]=t.y; }
#pragma unroll
            for (int l = 0; l < 4; ++l) {
                float a = m1v[l] - m2v[l];                 // sr
                float b = m3v[l] - m1v[l] - m2v[l];        // si
                float m2s = fmaf(a, a, b * b);
                m2s = fmaxf(m2s, 1e-37f);
                float rinv = rsqrtf(m2s);
                srv[e][l] = a; siv[e][l] = b; imv[e][l] = rinv;
                float mag = m2s * rinv;
                lmn[e] = fminf(lmn[e], mag);
                lmx[e] = fmaxf(lmx[e], mag);
            }
        }
        {   // publish P [k][q^swz]: pair (e0,e1) per store, 2-way conflicts max
            int swq = (2 * ty) ^ (4 * tx);    // sw(k)=4*((k>>2)&15)=4*tx for k=4tx+l
#pragma unroll
            for (int l = 0; l < 4; ++l) {
                int row = (4 * tx + l) * 64;
                *(float2*)&sm[PR_OFF + row + swq] = make_float2(srv[0][l], srv[1][l]);
                *(float2*)&sm[PI_OFF + row + swq] = make_float2(siv[0][l], siv[1][l]);
                *(float2*)&sm[IM_OFF + row + swq] = make_float2(imv[0][l], imv[1][l]);
            }
        }
#pragma unroll
        for (int off = 1; off < 16; off <<= 1) {
#pragma unroll
            for (int e = 0; e < 2; ++e) {
                lmn[e] = fminf(lmn[e], __shfl_xor_sync(0xffffffffu, lmn[e], off));
                lmx[e] = fmaxf(lmx[e], __shfl_xor_sync(0xffffffffu, lmx[e], off));
            }
        }
        if ((tid & 15) == 0) {
#pragma unroll
            for (int e = 0; e < 2; ++e) {
                int q = 2 * ty + e;
                sm[RMN_OFF + q] = fminf(sm[RMN_OFF + q], lmn[e]);
                sm[RMX_OFF + q] = fmaxf(sm[RMX_OFF + q], lmx[e]);
            }
        }
        __syncthreads();

        // ---- phase 2: Karatsuba A/B accumulation, packed over q-pair ----
#pragma unroll 2
        for (int k = 0; k < 64; ++k) {
            int swk = ((k >> 2) & 15) << 2;
            int pb = k * 64 + ((2 * ty) ^ swk);
            u64 prP = *(const u64*)&sm[PR_OFF + pb];
            u64 piP = *(const u64*)&sm[PI_OFF + pb];
            u64 imP = *(const u64*)&sm[IM_OFF + pb];
            u64 urP = mul2(prP, imP);
            u64 uiP = mul2(piP, imP);
            u64 psP = add2(prP, piP);
            u64 usP = add2(urP, uiP);
            int vb = 2 * (k * 64 + 4 * tx);
            ulonglong2 vra = *(const ulonglong2*)&sm[VR_OFF + vb];
            ulonglong2 vrb = *(const ulonglong2*)&sm[VR_OFF + vb + 4];
            ulonglong2 via = *(const ulonglong2*)&sm[VI_OFF + vb];
            ulonglong2 vib = *(const ulonglong2*)&sm[VI_OFF + vb + 4];
            ulonglong2 vsa = *(const ulonglong2*)&sm[VS_OFF + vb];
            ulonglong2 vsb = *(const ulonglong2*)&sm[VS_OFF + vb + 4];
            u64 vr2[4] = {vra.x, vra.y, vrb.x, vrb.y};
            u64 vi2[4] = {via.x, via.y, vib.x, vib.y};
            u64 vs2[4] = {vsa.x, vsa.y, vsb.x, vsb.y};
#pragma unroll
            for (int l = 0; l < 4; ++l) {
                M1a[l] = fma2(prP, vr2[l], M1a[l]);
                M2a[l] = fma2(piP, vi2[l], M2a[l]);
                M3a[l] = fma2(psP, vs2[l], M3a[l]);
                M1b[l] = fma2(urP, vr2[l], M1b[l]);
                M2b[l] = fma2(uiP, vi2[l], M2b[l]);
                M3b[l] = fma2(usP, vs2[l], M3b[l]);
            }
        }
    }

    // ---- epilogue: reconstruct A,B; out = (A - mn*B)/(mx - mn) ----
    float mn[2], mx[2], sc[2];
#pragma unroll
    for (int e = 0; e < 2; ++e) {
        int q = 2 * ty + e;
        mn[e] = sm[RMN_OFF + q];
        mx[e] = sm[RMX_OFF + q];
        sc[e] = 1.0f / (mx[e] - mn[e]);
    }
    float o_r[2][4], o_i[2][4];
#pragma unroll
    for (int l = 0; l < 4; ++l) {
        float2 a1 = unpack2(M1a[l]), a2 = unpack2(M2a[l]), a3 = unpack2(M3a[l]);
        float2 b1 = unpack2(M1b[l]), b2 = unpack2(M2b[l]), b3 = unpack2(M3b[l]);
        float ar0 = a1.x - a2.x, ai0 = a3.x - a1.x - a2.x;
        float br0 = b1.x - b2.x, bi0 = b3.x - b1.x - b2.x;
        o_r[0][l] = (ar0 - mn[0] * br0) * sc[0];
        o_i[0][l] = (ai0 - mn[0] * bi0) * sc[0];
        float ar1 = a1.y - a2.y, ai1 = a3.y - a1.y - a2.y;
        float br1 = b1.y - b2.y, bi1 = b3.y - b1.y - b2.y;
        o_r[1][l] = (ar1 - mn[1] * br1) * sc[1];
        o_i[1][l] = (ai1 - mn[1] * bi1) * sc[1];
    }
    float* out_r = out;
    float* out_i = out + (long)NHEADS * S_LEN * 64;
#pragma unroll
    for (int e = 0; e < 2; ++e) {
        int q = 2 * ty + e;
        long g = hb + (long)(qt * 64 + q) * 64 + 4 * tx;
        *(float4*)(out_r + g) = make_float4(o_r[e][0], o_r[e][1], o_r[e][2], o_r[e][3]);
        *(float4*)(out_i + g) = make_float4(o_i[e][0], o_i[e][1], o_i[e][2], o_i[e][3]);
    }
}

extern "C" void kernel_launch(void* const* d_in, const int* in_sizes, int n_in,
                              void* d_out, int out_size)
{
    const float* qr = (const float*)d_in[0];
    const float* qi = (const float*)d_in[1];
    const float* kr = (const float*)d_in[2];
    const float* ki = (const float*)d_in[3];
    const float* vr = (const float*)d_in[4];
    const float* vi = (const float*)d_in[5];
    float* out = (float*)d_out;

    const int smem_bytes = SMEM_FLOATS * (int)sizeof(float);   // 197,120 B
    cudaFuncSetAttribute(cvattn_kernel,
                         cudaFuncAttributeMaxDynamicSharedMemorySize, smem_bytes);

    dim3 grid(S_LEN / 64, NHEADS);   // 16 q-tiles × 64 heads
    cvattn_kernel<<<grid, NT, smem_bytes>>>(qr, qi, kr, ki, vr, vi, out);
}

// round 7
// speedup vs baseline: 1.9200x; 1.9200x over previous
#include <cuda_runtime.h>

// CVScaledDotProductAttention — one-pass: out = (A - mn*B)/(mx - mn)
//   A = sum_k attn*v, B = sum_k (attn/|attn|)*v, mn/mx = row min/max |attn|.
// R5: R2's scalar-FFMA structure (best L1-bytes/FLOP), smem shrunk via XOR
// swizzle (117.2KB -> 115.2KB) to fit 2 CTAs/SM -> 16 warps/SM.

#define TQ 64
#define TK 64
#define Dd 64
#define S_LEN 1024
#define NKT 16
#define NTHREADS 256
#define NHEADS 64

// smem layout (float offsets). K region aliased by P (never live together).
#define QR_OFF  0            // Q [d][q^swz], 4096
#define QI_OFF  4096
#define KR_OFF  8192         // K [d][k^swz], 4096   (aliased by P region)
#define KI_OFF  12288
#define PR_OFF  8192         // P real [q][k], stride 64
#define PI_OFF  12288
#define IM_OFF  16384        // 1/|s|
#define VR_OFF  20480        // V [k][d], stride 64
#define VI_OFF  24576
#define RMN_OFF 28672
#define RMX_OFF 28736
#define SMEM_FLOATS 28800    // 115,200 bytes -> 2 CTAs/SM

__global__ void __launch_bounds__(NTHREADS, 2)
cvattn_kernel(const float* __restrict__ qr_g, const float* __restrict__ qi_g,
              const float* __restrict__ kr_g, const float* __restrict__ ki_g,
              const float* __restrict__ vr_g, const float* __restrict__ vi_g,
              float* __restrict__ out)
{
    extern __shared__ float sm[];
    const int tid = threadIdx.x;
    const int tx = tid & 15;          // k / d fragment index (16)
    const int ty = tid >> 4;          // q fragment index (16)
    const int qt = blockIdx.x;        // q tile (16)
    const int head = blockIdx.y;      // 64 heads
    const long hb = (long)head * S_LEN * Dd;

    // ---- load Q tile, transposed to [d][q^swz], scaled by 1/TEMPERATURE ----
    // swizzle: element (d, c) lives at d*64 + (c ^ (d & 0x3C))
#pragma unroll
    for (int it = 0; it < 4; ++it) {
        int i  = tid + it * NTHREADS;       // 0..1023 float4 chunks
        int q  = i >> 4;
        int d4 = (i & 15) << 2;             // (d4+j) & 0x3C == d4 for j<4
        long g = hb + (long)(qt * TQ + q) * Dd + d4;
        float4 r4 = *(const float4*)(qr_g + g);
        float4 i4 = *(const float4*)(qi_g + g);
        int qs = q ^ d4;
        sm[QR_OFF + (d4 + 0) * 64 + qs] = r4.x * 0.125f;
        sm[QR_OFF + (d4 + 1) * 64 + qs] = r4.y * 0.125f;
        sm[QR_OFF + (d4 + 2) * 64 + qs] = r4.z * 0.125f;
        sm[QR_OFF + (d4 + 3) * 64 + qs] = r4.w * 0.125f;
        sm[QI_OFF + (d4 + 0) * 64 + qs] = i4.x * 0.125f;
        sm[QI_OFF + (d4 + 1) * 64 + qs] = i4.y * 0.125f;
        sm[QI_OFF + (d4 + 2) * 64 + qs] = i4.z * 0.125f;
        sm[QI_OFF + (d4 + 3) * 64 + qs] = i4.w * 0.125f;
    }
    if (tid < TQ) { sm[RMN_OFF + tid] = 3.0e38f; sm[RMX_OFF + tid] = -3.0e38f; }

    float Ar[4][4], Ai[4][4], Br[4][4], Bi[4][4];
#pragma unroll
    for (int j = 0; j < 4; ++j)
#pragma unroll
        for (int l = 0; l < 4; ++l) { Ar[j][l] = 0.f; Ai[j][l] = 0.f; Br[j][l] = 0.f; Bi[j][l] = 0.f; }

#pragma unroll 1
    for (int kt = 0; kt < NKT; ++kt) {
        __syncthreads();   // prev phase-2 finished with P/V region (and Q loads on kt=0)

        // ---- load K tile transposed to [d][k^swz], V tile natural [k][d] ----
#pragma unroll
        for (int it = 0; it < 4; ++it) {
            int i  = tid + it * NTHREADS;
            int k  = i >> 4;
            int d4 = (i & 15) << 2;
            long g = hb + (long)(kt * TK + k) * Dd + d4;
            float4 r4 = *(const float4*)(kr_g + g);
            float4 i4 = *(const float4*)(ki_g + g);
            int ks = k ^ d4;
            sm[KR_OFF + (d4 + 0) * 64 + ks] = r4.x;
            sm[KR_OFF + (d4 + 1) * 64 + ks] = r4.y;
            sm[KR_OFF + (d4 + 2) * 64 + ks] = r4.z;
            sm[KR_OFF + (d4 + 3) * 64 + ks] = r4.w;
            sm[KI_OFF + (d4 + 0) * 64 + ks] = i4.x;
            sm[KI_OFF + (d4 + 1) * 64 + ks] = i4.y;
            sm[KI_OFF + (d4 + 2) * 64 + ks] = i4.z;
            sm[KI_OFF + (d4 + 3) * 64 + ks] = i4.w;
            float4 vr4 = *(const float4*)(vr_g + g);
            float4 vi4 = *(const float4*)(vi_g + g);
            *(float4*)&sm[VR_OFF + k * Dd + d4] = vr4;
            *(float4*)&sm[VI_OFF + k * Dd + d4] = vi4;
        }
        __syncthreads();

        // ---- phase 1: complex scores S[4q][4k] per thread ----
        float sr[4][4], si[4][4];
#pragma unroll
        for (int j = 0; j < 4; ++j)
#pragma unroll
            for (int l = 0; l < 4; ++l) { sr[j][l] = 0.f; si[j][l] = 0.f; }

#pragma unroll 4
        for (int d = 0; d < Dd; ++d) {
            int sw = d & 0x3C;
            float4 qr4 = *(const float4*)&sm[QR_OFF + d * 64 + ((4 * ty) ^ sw)];
            float4 qi4 = *(const float4*)&sm[QI_OFF + d * 64 + ((4 * ty) ^ sw)];
            float4 kr4 = *(const float4*)&sm[KR_OFF + d * 64 + ((4 * tx) ^ sw)];
            float4 ki4 = *(const float4*)&sm[KI_OFF + d * 64 + ((4 * tx) ^ sw)];
            const float qr[4] = {qr4.x, qr4.y, qr4.z, qr4.w};
            const float qi[4] = {qi4.x, qi4.y, qi4.z, qi4.w};
            const float kr[4] = {kr4.x, kr4.y, kr4.z, kr4.w};
            const float ki[4] = {ki4.x, ki4.y, ki4.z, ki4.w};
#pragma unroll
            for (int j = 0; j < 4; ++j)
#pragma unroll
                for (int l = 0; l < 4; ++l) {
                    sr[j][l] = fmaf(qr[j], kr[l], sr[j][l]);
                    sr[j][l] = fmaf(-qi[j], ki[l], sr[j][l]);
                    si[j][l] = fmaf(qr[j], ki[l], si[j][l]);
                    si[j][l] = fmaf(qi[j], kr[l], si[j][l]);
                }
        }
        __syncthreads();   // K reads done; P/Im region may be overwritten

        // ---- phase 1.5: magnitudes, row min/max, publish P and 1/|s| ----
        float lmn[4], lmx[4];
#pragma unroll
        for (int j = 0; j < 4; ++j) {
            float imv[4], magv[4];
#pragma unroll
            for (int l = 0; l < 4; ++l) {
                float a = sr[j][l], b = si[j][l];
                float m2 = fmaf(a, a, b * b);
                m2 = fmaxf(m2, 1e-37f);
                float rinv = rsqrtf(m2);
                imv[l]  = rinv;
                magv[l] = m2 * rinv;
            }
            lmn[j] = fminf(fminf(magv[0], magv[1]), fminf(magv[2], magv[3]));
            lmx[j] = fmaxf(fmaxf(magv[0], magv[1]), fmaxf(magv[2], magv[3]));
            int qq = 4 * ty + j;
            *(float4*)&sm[PR_OFF + qq * TK + 4 * tx] = make_float4(sr[j][0], sr[j][1], sr[j][2], sr[j][3]);
            *(float4*)&sm[PI_OFF + qq * TK + 4 * tx] = make_float4(si[j][0], si[j][1], si[j][2], si[j][3]);
            *(float4*)&sm[IM_OFF + qq * TK + 4 * tx] = make_float4(imv[0], imv[1], imv[2], imv[3]);
        }
        // reduce min/max across the 16 tx lanes (xor stays inside 16-lane group)
#pragma unroll
        for (int off = 1; off < 16; off <<= 1) {
#pragma unroll
            for (int j = 0; j < 4; ++j) {
                lmn[j] = fminf(lmn[j], __shfl_xor_sync(0xffffffffu, lmn[j], off));
                lmx[j] = fmaxf(lmx[j], __shfl_xor_sync(0xffffffffu, lmx[j], off));
            }
        }
        if (tx == 0) {
#pragma unroll
            for (int j = 0; j < 4; ++j) {
                int qq = 4 * ty + j;
                sm[RMN_OFF + qq] = fminf(sm[RMN_OFF + qq], lmn[j]);
                sm[RMX_OFF + qq] = fmaxf(sm[RMX_OFF + qq], lmx[j]);
            }
        }
        __syncthreads();

        // ---- phase 2: A += P*V, B += (P/|P|)*V over this k tile ----
#pragma unroll 2
        for (int k = 0; k < TK; ++k) {
            float pr[4], pi[4], im[4];
#pragma unroll
            for (int j = 0; j < 4; ++j) {
                int qq = 4 * ty + j;                        // broadcast loads
                pr[j] = sm[PR_OFF + qq * TK + k];
                pi[j] = sm[PI_OFF + qq * TK + k];
                im[j] = sm[IM_OFF + qq * TK + k];
            }
            float4 vr4 = *(const float4*)&sm[VR_OFF + k * Dd + 4 * tx];
            float4 vi4 = *(const float4*)&sm[VI_OFF + k * Dd + 4 * tx];
            const float vr[4] = {vr4.x, vr4.y, vr4.z, vr4.w};
            const float vi[4] = {vi4.x, vi4.y, vi4.z, vi4.w};
            float ur[4], ui[4];
#pragma unroll
            for (int j = 0; j < 4; ++j) { ur[j] = pr[j] * im[j]; ui[j] = pi[j] * im[j]; }
#pragma unroll
            for (int j = 0; j < 4; ++j)
#pragma unroll
                for (int l = 0; l < 4; ++l) {
                    Ar[j][l] = fmaf(pr[j], vr[l], Ar[j][l]);
                    Ar[j][l] = fmaf(-pi[j], vi[l], Ar[j][l]);
                    Ai[j][l] = fmaf(pr[j], vi[l], Ai[j][l]);
                    Ai[j][l] = fmaf(pi[j], vr[l], Ai[j][l]);
                    Br[j][l] = fmaf(ur[j], vr[l], Br[j][l]);
                    Br[j][l] = fmaf(-ui[j], vi[l], Br[j][l]);
                    Bi[j][l] = fmaf(ur[j], vi[l], Bi[j][l]);
                    Bi[j][l] = fmaf(ui[j], vr[l], Bi[j][l]);
                }
        }
    }
    __syncthreads();

    // ---- epilogue: out = (A - mn*B) / (mx - mn) ----
    float* out_r = out;
    float* out_i = out + (long)NHEADS * S_LEN * Dd;
#pragma unroll
    for (int j = 0; j < 4; ++j) {
        int qq = 4 * ty + j;
        float mn = sm[RMN_OFF + qq];
        float mx = sm[RMX_OFF + qq];
        float sc = 1.0f / (mx - mn);
        float4 o_r, o_i;
        o_r.x = (Ar[j][0] - mn * Br[j][0]) * sc;
        o_r.y = (Ar[j][1] - mn * Br[j][1]) * sc;
        o_r.z = (Ar[j][2] - mn * Br[j][2]) * sc;
        o_r.w = (Ar[j][3] - mn * Br[j][3]) * sc;
        o_i.x = (Ai[j][0] - mn * Bi[j][0]) * sc;
        o_i.y = (Ai[j][1] - mn * Bi[j][1]) * sc;
        o_i.z = (Ai[j][2] - mn * Bi[j][2]) * sc;
        o_i.w = (Ai[j][3] - mn * Bi[j][3]) * sc;
        long g = hb + (long)(qt * TQ + qq) * Dd + 4 * tx;
        *(float4*)(out_r + g) = o_r;
        *(float4*)(out_i + g) = o_i;
    }
}

extern "C" void kernel_launch(void* const* d_in, const int* in_sizes, int n_in,
                              void* d_out, int out_size)
{
    const float* qr = (const float*)d_in[0];
    const float* qi = (const float*)d_in[1];
    const float* kr = (const float*)d_in[2];
    const float* ki = (const float*)d_in[3];
    const float* vr = (const float*)d_in[4];
    const float* vi = (const float*)d_in[5];
    float* out = (float*)d_out;

    const int smem_bytes = SMEM_FLOATS * (int)sizeof(float);   // 115,200 B
    cudaFuncSetAttribute(cvattn_kernel,
                         cudaFuncAttributeMaxDynamicSharedMemorySize, smem_bytes);

    dim3 grid(S_LEN / TQ, NHEADS);   // (16 q-tiles, 64 heads)
    cvattn_kernel<<<grid, NTHREADS, smem_bytes>>>(qr, qi, kr, ki, vr, vi, out);
}

// round 9
// speedup vs baseline: 1.9207x; 1.0004x over previous
#include <cuda_runtime.h>

// CVScaledDotProductAttention — one-pass: out = (A - mn*B)/(mx - mn)
//   A = sum_k attn*v, B = sum_k (attn/|attn|)*v, mn/mx = row min/max |attn|.
// R5: R2's scalar-FFMA structure (best L1-bytes/FLOP), smem shrunk via XOR
// swizzle (117.2KB -> 115.2KB) to fit 2 CTAs/SM -> 16 warps/SM.

#define TQ 64
#define TK 64
#define Dd 64
#define S_LEN 1024
#define NKT 16
#define NTHREADS 256
#define NHEADS 64

// smem layout (float offsets). K region aliased by P (never live together).
#define QR_OFF  0            // Q [d][q^swz], 4096
#define QI_OFF  4096
#define KR_OFF  8192         // K [d][k^swz], 4096   (aliased by P region)
#define KI_OFF  12288
#define PR_OFF  8192         // P real [q][k], stride 64
#define PI_OFF  12288
#define IM_OFF  16384        // 1/|s|
#define VR_OFF  20480        // V [k][d], stride 64
#define VI_OFF  24576
#define RMN_OFF 28672
#define RMX_OFF 28736
#define SMEM_FLOATS 28800    // 115,200 bytes -> 2 CTAs/SM

__global__ void __launch_bounds__(NTHREADS, 2)
cvattn_kernel(const float* __restrict__ qr_g, const float* __restrict__ qi_g,
              const float* __restrict__ kr_g, const float* __restrict__ ki_g,
              const float* __restrict__ vr_g, const float* __restrict__ vi_g,
              float* __restrict__ out)
{
    extern __shared__ float sm[];
    const int tid = threadIdx.x;
    const int tx = tid & 15;          // k / d fragment index (16)
    const int ty = tid >> 4;          // q fragment index (16)
    const int qt = blockIdx.x;        // q tile (16)
    const int head = blockIdx.y;      // 64 heads
    const long hb = (long)head * S_LEN * Dd;

    // ---- load Q tile, transposed to [d][q^swz], scaled by 1/TEMPERATURE ----
    // swizzle: element (d, c) lives at d*64 + (c ^ (d & 0x3C))
#pragma unroll
    for (int it = 0; it < 4; ++it) {
        int i  = tid + it * NTHREADS;       // 0..1023 float4 chunks
        int q  = i >> 4;
        int d4 = (i & 15) << 2;             // (d4+j) & 0x3C == d4 for j<4
        long g = hb + (long)(qt * TQ + q) * Dd + d4;
        float4 r4 = *(const float4*)(qr_g + g);
        float4 i4 = *(const float4*)(qi_g + g);
        int qs = q ^ d4;
        sm[QR_OFF + (d4 + 0) * 64 + qs] = r4.x * 0.125f;
        sm[QR_OFF + (d4 + 1) * 64 + qs] = r4.y * 0.125f;
        sm[QR_OFF + (d4 + 2) * 64 + qs] = r4.z * 0.125f;
        sm[QR_OFF + (d4 + 3) * 64 + qs] = r4.w * 0.125f;
        sm[QI_OFF + (d4 + 0) * 64 + qs] = i4.x * 0.125f;
        sm[QI_OFF + (d4 + 1) * 64 + qs] = i4.y * 0.125f;
        sm[QI_OFF + (d4 + 2) * 64 + qs] = i4.z * 0.125f;
        sm[QI_OFF + (d4 + 3) * 64 + qs] = i4.w * 0.125f;
    }
    if (tid < TQ) { sm[RMN_OFF + tid] = 3.0e38f; sm[RMX_OFF + tid] = -3.0e38f; }

    float Ar[4][4], Ai[4][4], Br[4][4], Bi[4][4];
#pragma unroll
    for (int j = 0; j < 4; ++j)
#pragma unroll
        for (int l = 0; l < 4; ++l) { Ar[j][l] = 0.f; Ai[j][l] = 0.f; Br[j][l] = 0.f; Bi[j][l] = 0.f; }

#pragma unroll 1
    for (int kt = 0; kt < NKT; ++kt) {
        __syncthreads();   // prev phase-2 finished with P/V region (and Q loads on kt=0)

        // ---- load K tile transposed to [d][k^swz], V tile natural [k][d] ----
#pragma unroll
        for (int it = 0; it < 4; ++it) {
            int i  = tid + it * NTHREADS;
            int k  = i >> 4;
            int d4 = (i & 15) << 2;
            long g = hb + (long)(kt * TK + k) * Dd + d4;
            float4 r4 = *(const float4*)(kr_g + g);
            float4 i4 = *(const float4*)(ki_g + g);
            int ks = k ^ d4;
            sm[KR_OFF + (d4 + 0) * 64 + ks] = r4.x;
            sm[KR_OFF + (d4 + 1) * 64 + ks] = r4.y;
            sm[KR_OFF + (d4 + 2) * 64 + ks] = r4.z;
            sm[KR_OFF + (d4 + 3) * 64 + ks] = r4.w;
            sm[KI_OFF + (d4 + 0) * 64 + ks] = i4.x;
            sm[KI_OFF + (d4 + 1) * 64 + ks] = i4.y;
            sm[KI_OFF + (d4 + 2) * 64 + ks] = i4.z;
            sm[KI_OFF + (d4 + 3) * 64 + ks] = i4.w;
            float4 vr4 = *(const float4*)(vr_g + g);
            float4 vi4 = *(const float4*)(vi_g + g);
            *(float4*)&sm[VR_OFF + k * Dd + d4] = vr4;
            *(float4*)&sm[VI_OFF + k * Dd + d4] = vi4;
        }
        __syncthreads();

        // ---- phase 1: complex scores S[4q][4k] per thread ----
        float sr[4][4], si[4][4];
#pragma unroll
        for (int j = 0; j < 4; ++j)
#pragma unroll
            for (int l = 0; l < 4; ++l) { sr[j][l] = 0.f; si[j][l] = 0.f; }

#pragma unroll 4
        for (int d = 0; d < Dd; ++d) {
            int sw = d & 0x3C;
            float4 qr4 = *(const float4*)&sm[QR_OFF + d * 64 + ((4 * ty) ^ sw)];
            float4 qi4 = *(const float4*)&sm[QI_OFF + d * 64 + ((4 * ty) ^ sw)];
            float4 kr4 = *(const float4*)&sm[KR_OFF + d * 64 + ((4 * tx) ^ sw)];
            float4 ki4 = *(const float4*)&sm[KI_OFF + d * 64 + ((4 * tx) ^ sw)];
            const float qr[4] = {qr4.x, qr4.y, qr4.z, qr4.w};
            const float qi[4] = {qi4.x, qi4.y, qi4.z, qi4.w};
            const float kr[4] = {kr4.x, kr4.y, kr4.z, kr4.w};
            const float ki[4] = {ki4.x, ki4.y, ki4.z, ki4.w};
#pragma unroll
            for (int j = 0; j < 4; ++j)
#pragma unroll
                for (int l = 0; l < 4; ++l) {
                    sr[j][l] = fmaf(qr[j], kr[l], sr[j][l]);
                    sr[j][l] = fmaf(-qi[j], ki[l], sr[j][l]);
                    si[j][l] = fmaf(qr[j], ki[l], si[j][l]);
                    si[j][l] = fmaf(qi[j], kr[l], si[j][l]);
                }
        }
        __syncthreads();   // K reads done; P/Im region may be overwritten

        // ---- phase 1.5: magnitudes, row min/max, publish P and 1/|s| ----
        float lmn[4], lmx[4];
#pragma unroll
        for (int j = 0; j < 4; ++j) {
            float imv[4], magv[4];
#pragma unroll
            for (int l = 0; l < 4; ++l) {
                float a = sr[j][l], b = si[j][l];
                float m2 = fmaf(a, a, b * b);
                m2 = fmaxf(m2, 1e-37f);
                float rinv = rsqrtf(m2);
                imv[l]  = rinv;
                magv[l] = m2 * rinv;
            }
            lmn[j] = fminf(fminf(magv[0], magv[1]), fminf(magv[2], magv[3]));
            lmx[j] = fmaxf(fmaxf(magv[0], magv[1]), fmaxf(magv[2], magv[3]));
            int qq = 4 * ty + j;
            *(float4*)&sm[PR_OFF + qq * TK + 4 * tx] = make_float4(sr[j][0], sr[j][1], sr[j][2], sr[j][3]);
            *(float4*)&sm[PI_OFF + qq * TK + 4 * tx] = make_float4(si[j][0], si[j][1], si[j][2], si[j][3]);
            *(float4*)&sm[IM_OFF + qq * TK + 4 * tx] = make_float4(imv[0], imv[1], imv[2], imv[3]);
        }
        // reduce min/max across the 16 tx lanes (xor stays inside 16-lane group)
#pragma unroll
        for (int off = 1; off < 16; off <<= 1) {
#pragma unroll
            for (int j = 0; j < 4; ++j) {
                lmn[j] = fminf(lmn[j], __shfl_xor_sync(0xffffffffu, lmn[j], off));
                lmx[j] = fmaxf(lmx[j], __shfl_xor_sync(0xffffffffu, lmx[j], off));
            }
        }
        if (tx == 0) {
#pragma unroll
            for (int j = 0; j < 4; ++j) {
                int qq = 4 * ty + j;
                sm[RMN_OFF + qq] = fminf(sm[RMN_OFF + qq], lmn[j]);
                sm[RMX_OFF + qq] = fmaxf(sm[RMX_OFF + qq], lmx[j]);
            }
        }
        __syncthreads();

        // ---- phase 2: A += P*V, B += (P/|P|)*V over this k tile ----
#pragma unroll 2
        for (int k = 0; k < TK; ++k) {
            float pr[4], pi[4], im[4];
#pragma unroll
            for (int j = 0; j < 4; ++j) {
                int qq = 4 * ty + j;                        // broadcast loads
                pr[j] = sm[PR_OFF + qq * TK + k];
                pi[j] = sm[PI_OFF + qq * TK + k];
                im[j] = sm[IM_OFF + qq * TK + k];
            }
            float4 vr4 = *(const float4*)&sm[VR_OFF + k * Dd + 4 * tx];
            float4 vi4 = *(const float4*)&sm[VI_OFF + k * Dd + 4 * tx];
            const float vr[4] = {vr4.x, vr4.y, vr4.z, vr4.w};
            const float vi[4] = {vi4.x, vi4.y, vi4.z, vi4.w};
            float ur[4], ui[4];
#pragma unroll
            for (int j = 0; j < 4; ++j) { ur[j] = pr[j] * im[j]; ui[j] = pi[j] * im[j]; }
#pragma unroll
            for (int j = 0; j < 4; ++j)
#pragma unroll
                for (int l = 0; l < 4; ++l) {
                    Ar[j][l] = fmaf(pr[j], vr[l], Ar[j][l]);
                    Ar[j][l] = fmaf(-pi[j], vi[l], Ar[j][l]);
                    Ai[j][l] = fmaf(pr[j], vi[l], Ai[j][l]);
                    Ai[j][l] = fmaf(pi[j], vr[l], Ai[j][l]);
                    Br[j][l] = fmaf(ur[j], vr[l], Br[j][l]);
                    Br[j][l] = fmaf(-ui[j], vi[l], Br[j][l]);
                    Bi[j][l] = fmaf(ur[j], vi[l], Bi[j][l]);
                    Bi[j][l] = fmaf(ui[j], vr[l], Bi[j][l]);
                }
        }
    }
    __syncthreads();

    // ---- epilogue: out = (A - mn*B) / (mx - mn) ----
    float* out_r = out;
    float* out_i = out + (long)NHEADS * S_LEN * Dd;
#pragma unroll
    for (int j = 0; j < 4; ++j) {
        int qq = 4 * ty + j;
        float mn = sm[RMN_OFF + qq];
        float mx = sm[RMX_OFF + qq];
        float sc = 1.0f / (mx - mn);
        float4 o_r, o_i;
        o_r.x = (Ar[j][0] - mn * Br[j][0]) * sc;
        o_r.y = (Ar[j][1] - mn * Br[j][1]) * sc;
        o_r.z = (Ar[j][2] - mn * Br[j][2]) * sc;
        o_r.w = (Ar[j][3] - mn * Br[j][3]) * sc;
        o_i.x = (Ai[j][0] - mn * Bi[j][0]) * sc;
        o_i.y = (Ai[j][1] - mn * Bi[j][1]) * sc;
        o_i.z = (Ai[j][2] - mn * Bi[j][2]) * sc;
        o_i.w = (Ai[j][3] - mn * Bi[j][3]) * sc;
        long g = hb + (long)(qt * TQ + qq) * Dd + 4 * tx;
        *(float4*)(out_r + g) = o_r;
        *(float4*)(out_i + g) = o_i;
    }
}

extern "C" void kernel_launch(void* const* d_in, const int* in_sizes, int n_in,
                              void* d_out, int out_size)
{
    const float* qr = (const float*)d_in[0];
    const float* qi = (const float*)d_in[1];
    const float* kr = (const float*)d_in[2];
    const float* ki = (const float*)d_in[3];
    const float* vr = (const float*)d_in[4];
    const float* vi = (const float*)d_in[5];
    float* out = (float*)d_out;

    const int smem_bytes = SMEM_FLOATS * (int)sizeof(float);   // 115,200 B
    cudaFuncSetAttribute(cvattn_kernel,
                         cudaFuncAttributeMaxDynamicSharedMemorySize, smem_bytes);

    dim3 grid(S_LEN / TQ, NHEADS);   // (16 q-tiles, 64 heads)
    cvattn_kernel<<<grid, NTHREADS, smem_bytes>>>(qr, qi, kr, ki, vr, vi, out);
}

// round 11
// speedup vs baseline: 4.7299x; 2.4625x over previous
#include <cuda_runtime.h>
#include <cuda_bf16.h>
#include <mma.h>
#include <stdint.h>

using namespace nvcuda;

#define S_LEN 1024
#define NHEADS 64
#define NT 256
#define NKT 16
#define LB 72   // bf16 leading dim (64+8)
#define LF 72   // fp32 leading dim

// smem byte offsets (all 32B-aligned); bf16 tile = 64*72*2 = 9216 B, fp32 = 18432 B
#define QRH 0
#define QRL 9216
#define QIH 18432
#define QIL 27648
#define KRH 36864
#define KRL 46080
#define KIH 55296
#define KIL 64512
#define KNH 73728
#define KNL 82944
#define PRH 36864      // P region aliases K region (never live together)
#define PRL 46080
#define PIH 55296
#define PIL 64512
#define URO 73728
#define UIO 82944
#define VRH 92160
#define VRL 101376
#define VIH 110592
#define VIL 119808
#define VNH 129024
#define VNL 138240
#define SRO 147456     // scores fp32
#define SIO 165888
#define OAR 147456     // final accum stores alias S and P regions
#define OAI 165888
#define OBR 36864
#define OBI 55296
#define RMN 184320     // [4][64] fp32
#define RMX 185344
#define SMEM_BYTES 186368

#define BF(off) ((__nv_bfloat16*)(smc + (off)))
#define FP(off) ((float*)(smc + (off)))

typedef wmma::fragment<wmma::matrix_a, 16, 16, 16, __nv_bfloat16, wmma::row_major> FragA;
typedef wmma::fragment<wmma::matrix_b, 16, 16, 16, __nv_bfloat16, wmma::col_major> FragBc;
typedef wmma::fragment<wmma::matrix_b, 16, 16, 16, __nv_bfloat16, wmma::row_major> FragBr;
typedef wmma::fragment<wmma::accumulator, 16, 16, 16, float> FragC;

__device__ __forceinline__ uint2 h4(float4 v) {
    __nv_bfloat162 a = __floats2bfloat162_rn(v.x, v.y);
    __nv_bfloat162 b = __floats2bfloat162_rn(v.z, v.w);
    uint2 r; r.x = *(uint32_t*)&a; r.y = *(uint32_t*)&b; return r;
}
__device__ __forceinline__ float4 resid(float4 v, uint2 h) {
    __nv_bfloat162 a = *(__nv_bfloat162*)&h.x, b = *(__nv_bfloat162*)&h.y;
    return make_float4(v.x - __bfloat162float(a.x), v.y - __bfloat162float(a.y),
                       v.z - __bfloat162float(b.x), v.w - __bfloat162float(b.y));
}
__device__ __forceinline__ uint2 neg2(uint2 v) {
    return make_uint2(v.x ^ 0x80008000u, v.y ^ 0x80008000u);
}

__global__ void __launch_bounds__(NT)
cvattn_wm(const float* __restrict__ qr_g, const float* __restrict__ qi_g,
          const float* __restrict__ kr_g, const float* __restrict__ ki_g,
          const float* __restrict__ vr_g, const float* __restrict__ vi_g,
          float* __restrict__ out)
{
    extern __shared__ char smc[];
    const int tid = threadIdx.x;
    const int wid = tid >> 5;
    const int fr  = wid >> 1;            // frag row 0..3 (16 q each)
    const int fc0 = (wid & 1) * 2;       // frag col base 0 or 2
    const int qt = blockIdx.x, head = blockIdx.y;
    const long hb = (long)head * S_LEN * 64;

    // ---- load Q (scaled 1/8), split hi/lo bf16, row-major [q][d] ----
#pragma unroll
    for (int it = 0; it < 4; ++it) {
        int c = it * NT + tid;                 // 1024 float4 chunks
        int q = c >> 4, d4 = (c & 15) << 2;
        long g = hb + (long)(qt * 64 + q) * 64 + d4;
        float4 r4 = *(const float4*)(qr_g + g);
        float4 i4 = *(const float4*)(qi_g + g);
        r4.x *= 0.125f; r4.y *= 0.125f; r4.z *= 0.125f; r4.w *= 0.125f;
        i4.x *= 0.125f; i4.y *= 0.125f; i4.z *= 0.125f; i4.w *= 0.125f;
        int idx = q * LB + d4;
        uint2 h = h4(r4);
        *(uint2*)(BF(QRH) + idx) = h;
        *(uint2*)(BF(QRL) + idx) = h4(resid(r4, h));
        h = h4(i4);
        *(uint2*)(BF(QIH) + idx) = h;
        *(uint2*)(BF(QIL) + idx) = h4(resid(i4, h));
    }

    FragC ar[2], ai[2], br[2], bi[2];
#pragma unroll
    for (int c = 0; c < 2; ++c) {
        wmma::fill_fragment(ar[c], 0.f); wmma::fill_fragment(ai[c], 0.f);
        wmma::fill_fragment(br[c], 0.f); wmma::fill_fragment(bi[c], 0.f);
    }
    float mnp = 3.0e38f, mxp = -3.0e38f;
    const int erow = tid >> 2, eseg = tid & 3;   // fixed (row,seg) ownership

#pragma unroll 1
    for (int kt = 0; kt < NKT; ++kt) {
        __syncthreads();   // prev PV frag loads done before K/P/V overwrite

        // ---- load K (+kn=-ki) and V (+vn=-vi), split hi/lo, [k][d] row-major ----
        long kb = hb + (long)(kt * 64) * 64;
#pragma unroll
        for (int it = 0; it < 4; ++it) {
            int c = it * NT + tid;
            int k = c >> 4, d4 = (c & 15) << 2;
            long g = kb + (long)k * 64 + d4;
            int idx = k * LB + d4;
            float4 r4 = *(const float4*)(kr_g + g);
            float4 i4 = *(const float4*)(ki_g + g);
            uint2 h = h4(r4);
            *(uint2*)(BF(KRH) + idx) = h;
            *(uint2*)(BF(KRL) + idx) = h4(resid(r4, h));
            h = h4(i4);
            *(uint2*)(BF(KIH) + idx) = h;
            *(uint2*)(BF(KNH) + idx) = neg2(h);
            uint2 hl = h4(resid(i4, h));
            *(uint2*)(BF(KIL) + idx) = hl;
            *(uint2*)(BF(KNL) + idx) = neg2(hl);
            r4 = *(const float4*)(vr_g + g);
            i4 = *(const float4*)(vi_g + g);
            h = h4(r4);
            *(uint2*)(BF(VRH) + idx) = h;
            *(uint2*)(BF(VRL) + idx) = h4(resid(r4, h));
            h = h4(i4);
            *(uint2*)(BF(VIH) + idx) = h;
            *(uint2*)(BF(VNH) + idx) = neg2(h);
            hl = h4(resid(i4, h));
            *(uint2*)(BF(VIL) + idx) = hl;
            *(uint2*)(BF(VNL) + idx) = neg2(hl);
        }
        __syncthreads();

        // ---- scores: sr = qr*kr + qi*(-ki), si = qr*ki + qi*kr (split 3-term) ----
        {
            FragC s_r[2], s_i[2];
            wmma::fill_fragment(s_r[0], 0.f); wmma::fill_fragment(s_r[1], 0.f);
            wmma::fill_fragment(s_i[0], 0.f); wmma::fill_fragment(s_i[1], 0.f);
#pragma unroll
            for (int ks = 0; ks < 4; ++ks) {
                const int ao = fr * 16 * LB + ks * 16;
                FragA aqrh, aqrl, aqih, aqil;
                wmma::load_matrix_sync(aqrh, BF(QRH) + ao, LB);
                wmma::load_matrix_sync(aqrl, BF(QRL) + ao, LB);
                wmma::load_matrix_sync(aqih, BF(QIH) + ao, LB);
                wmma::load_matrix_sync(aqil, BF(QIL) + ao, LB);
#pragma unroll
                for (int c = 0; c < 2; ++c) {
                    const int bo = (fc0 + c) * 16 * LB + ks * 16;  // K^T col_major
                    FragBc bkrh, bkrl, bkih, bkil, bknh, bknl;
                    wmma::load_matrix_sync(bkrh, BF(KRH) + bo, LB);
                    wmma::load_matrix_sync(bkrl, BF(KRL) + bo, LB);
                    wmma::load_matrix_sync(bkih, BF(KIH) + bo, LB);
                    wmma::load_matrix_sync(bkil, BF(KIL) + bo, LB);
                    wmma::load_matrix_sync(bknh, BF(KNH) + bo, LB);
                    wmma::load_matrix_sync(bknl, BF(KNL) + bo, LB);
                    wmma::mma_sync(s_r[c], aqrh, bkrh, s_r[c]);
                    wmma::mma_sync(s_r[c], aqrh, bkrl, s_r[c]);
                    wmma::mma_sync(s_r[c], aqrl, bkrh, s_r[c]);
                    wmma::mma_sync(s_r[c], aqih, bknh, s_r[c]);
                    wmma::mma_sync(s_r[c], aqih, bknl, s_r[c]);
                    wmma::mma_sync(s_r[c], aqil, bknh, s_r[c]);
                    wmma::mma_sync(s_i[c], aqrh, bkih, s_i[c]);
                    wmma::mma_sync(s_i[c], aqrh, bkil, s_i[c]);
                    wmma::mma_sync(s_i[c], aqrl, bkih, s_i[c]);
                    wmma::mma_sync(s_i[c], aqih, bkrh, s_i[c]);
                    wmma::mma_sync(s_i[c], aqih, bkrl, s_i[c]);
                    wmma::mma_sync(s_i[c], aqil, bkrh, s_i[c]);
                }
            }
#pragma unroll
            for (int c = 0; c < 2; ++c) {
                const int so = fr * 16 * LF + (fc0 + c) * 16;
                wmma::store_matrix_sync(FP(SRO) + so, s_r[c], LF, wmma::mem_row_major);
                wmma::store_matrix_sync(FP(SIO) + so, s_i[c], LF, wmma::mem_row_major);
            }
        }
        __syncthreads();

        // ---- epilogue: mag, running min/max (register), split-P + U to smem ----
        {
            const float* srp = FP(SRO) + erow * LF + eseg * 16;
            const float* sip = FP(SIO) + erow * LF + eseg * 16;
            const int pb = erow * LB + eseg * 16;
#pragma unroll
            for (int i = 0; i < 4; ++i) {
                float4 a4 = *(const float4*)(srp + 4 * i);
                float4 b4 = *(const float4*)(sip + 4 * i);
                float4 ur4, ui4;
                float m2, rv, mg;
#define DOEL(X) m2 = fmaf(a4.X, a4.X, b4.X * b4.X); m2 = fmaxf(m2, 1e-37f); \
                rv = rsqrtf(m2); mg = m2 * rv; mnp = fminf(mnp, mg); mxp = fmaxf(mxp, mg); \
                ur4.X = a4.X * rv; ui4.X = b4.X * rv;
                DOEL(x) DOEL(y) DOEL(z) DOEL(w)
#undef DOEL
                uint2 h = h4(a4);
                *(uint2*)(BF(PRH) + pb + 4 * i) = h;
                *(uint2*)(BF(PRL) + pb + 4 * i) = h4(resid(a4, h));
                h = h4(b4);
                *(uint2*)(BF(PIH) + pb + 4 * i) = h;
                *(uint2*)(BF(PIL) + pb + 4 * i) = h4(resid(b4, h));
                *(uint2*)(BF(URO) + pb + 4 * i) = h4(ur4);
                *(uint2*)(BF(UIO) + pb + 4 * i) = h4(ui4);
            }
        }
        __syncthreads();

        // ---- PV: A += P*V (split), B += U*V (bf16) ----
#pragma unroll
        for (int ks = 0; ks < 4; ++ks) {
            const int ao = fr * 16 * LB + ks * 16;
            FragA aprh, aprl, apih, apil, aur, aui;
            wmma::load_matrix_sync(aprh, BF(PRH) + ao, LB);
            wmma::load_matrix_sync(aprl, BF(PRL) + ao, LB);
            wmma::load_matrix_sync(apih, BF(PIH) + ao, LB);
            wmma::load_matrix_sync(apil, BF(PIL) + ao, LB);
            wmma::load_matrix_sync(aur,  BF(URO) + ao, LB);
            wmma::load_matrix_sync(aui,  BF(UIO) + ao, LB);
#pragma unroll
            for (int c = 0; c < 2; ++c) {
                const int bo = ks * 16 * LB + (fc0 + c) * 16;   // V row_major
                FragBr bvrh, bvrl, bvih, bvil, bvnh, bvnl;
                wmma::load_matrix_sync(bvrh, BF(VRH) + bo, LB);
                wmma::load_matrix_sync(bvrl, BF(VRL) + bo, LB);
                wmma::load_matrix_sync(bvih, BF(VIH) + bo, LB);
                wmma::load_matrix_sync(bvil, BF(VIL) + bo, LB);
                wmma::load_matrix_sync(bvnh, BF(VNH) + bo, LB);
                wmma::load_matrix_sync(bvnl, BF(VNL) + bo, LB);
                wmma::mma_sync(ar[c], aprh, bvrh, ar[c]);
                wmma::mma_sync(ar[c], aprh, bvrl, ar[c]);
                wmma::mma_sync(ar[c], aprl, bvrh, ar[c]);
                wmma::mma_sync(ar[c], apih, bvnh, ar[c]);
                wmma::mma_sync(ar[c], apih, bvnl, ar[c]);
                wmma::mma_sync(ar[c], apil, bvnh, ar[c]);
                wmma::mma_sync(ai[c], aprh, bvih, ai[c]);
                wmma::mma_sync(ai[c], aprh, bvil, ai[c]);
                wmma::mma_sync(ai[c], aprl, bvih, ai[c]);
                wmma::mma_sync(ai[c], apih, bvrh, ai[c]);
                wmma::mma_sync(ai[c], apih, bvrl, ai[c]);
                wmma::mma_sync(ai[c], apil, bvrh, ai[c]);
                wmma::mma_sync(br[c], aur, bvrh, br[c]);
                wmma::mma_sync(br[c], aui, bvnh, br[c]);
                wmma::mma_sync(bi[c], aur, bvih, bi[c]);
                wmma::mma_sync(bi[c], aui, bvrh, bi[c]);
            }
        }
    }
    __syncthreads();   // all PV loads done before aliased accum stores

    // ---- store accumulators + min/max partials ----
#pragma unroll
    for (int c = 0; c < 2; ++c) {
        const int so = fr * 16 * LF + (fc0 + c) * 16;
        wmma::store_matrix_sync(FP(OAR) + so, ar[c], LF, wmma::mem_row_major);
        wmma::store_matrix_sync(FP(OAI) + so, ai[c], LF, wmma::mem_row_major);
        wmma::store_matrix_sync(FP(OBR) + so, br[c], LF, wmma::mem_row_major);
        wmma::store_matrix_sync(FP(OBI) + so, bi[c], LF, wmma::mem_row_major);
    }
    FP(RMN)[eseg * 64 + erow] = mnp;
    FP(RMX)[eseg * 64 + erow] = mxp;
    __syncthreads();

    // ---- final: out = (A - mn*B)/(mx - mn), coalesced ----
    float* out_r = out;
    float* out_i = out + (long)NHEADS * S_LEN * 64;
#pragma unroll
    for (int it = 0; it < 4; ++it) {
        int c = it * NT + tid;
        int row = c >> 4, c4 = (c & 15) << 2;
        float mn = fminf(fminf(FP(RMN)[row], FP(RMN)[64 + row]),
                         fminf(FP(RMN)[128 + row], FP(RMN)[192 + row]));
        float mx = fmaxf(fmaxf(FP(RMX)[row], FP(RMX)[64 + row]),
                         fmaxf(FP(RMX)[128 + row], FP(RMX)[192 + row]));
        float isc = 1.0f / (mx - mn);
        float4 A_r = *(const float4*)(FP(OAR) + row * LF + c4);
        float4 A_i = *(const float4*)(FP(OAI) + row * LF + c4);
        float4 B_r = *(const float4*)(FP(OBR) + row * LF + c4);
        float4 B_i = *(const float4*)(FP(OBI) + row * LF + c4);
        float4 o_r, o_i;
        o_r.x = (A_r.x - mn * B_r.x) * isc; o_r.y = (A_r.y - mn * B_r.y) * isc;
        o_r.z = (A_r.z - mn * B_r.z) * isc; o_r.w = (A_r.w - mn * B_r.w) * isc;
        o_i.x = (A_i.x - mn * B_i.x) * isc; o_i.y = (A_i.y - mn * B_i.y) * isc;
        o_i.z = (A_i.z - mn * B_i.z) * isc; o_i.w = (A_i.w - mn * B_i.w) * isc;
        long g = hb + (long)(qt * 64 + row) * 64 + c4;
        *(float4*)(out_r + g) = o_r;
        *(float4*)(out_i + g) = o_i;
    }
}

extern "C" void kernel_launch(void* const* d_in, const int* in_sizes, int n_in,
                              void* d_out, int out_size)
{
    const float* qr = (const float*)d_in[0];
    const float* qi = (const float*)d_in[1];
    const float* kr = (const float*)d_in[2];
    const float* ki = (const float*)d_in[3];
    const float* vr = (const float*)d_in[4];
    const float* vi = (const float*)d_in[5];
    float* out = (float*)d_out;

    cudaFuncSetAttribute(cvattn_wm, cudaFuncAttributeMaxDynamicSharedMemorySize, SMEM_BYTES);
    dim3 grid(S_LEN / 64, NHEADS);   // 16 q-tiles x 64 heads
    cvattn_wm<<<grid, NT, SMEM_BYTES>>>(qr, qi, kr, ki, vr, vi, out);
}